// round 2
// baseline (speedup 1.0000x reference)
#include <cuda_runtime.h>
#include <cstdint>

// Problem: B=8, S=128, V=32000, E=768
// input:  one-hot [B,S,V] f32  (B*S*V = 32,768,000 elements)
// weight: [V,E] f32            (V*E   = 24,576,000 elements)
// out:    [B,S,E] f32          (B*S*E =    786,432 elements)
//
// out[b,s,:] = weight[argnonzero(input[b,s,:]), :]   (exact gather; one-hot is 0/1)

#define NROWS   1024          // B*S
#define VEC_V   8000          // V/4 float4 per row
#define VEC_E   192           // E/4 float4 per row
#define THREADS 256

__global__ __launch_bounds__(THREADS)
void onehot_embed_kernel(const float4* __restrict__ oh,
                         const float4* __restrict__ w,
                         float4* __restrict__ out)
{
    __shared__ int s_idx;
    const int row = blockIdx.x;
    if (threadIdx.x == 0) s_idx = 0;
    __syncthreads();

    // ---- scan this row's 32000 floats (8000 float4) for the nonzero ----
    const float4* r = oh + (size_t)row * VEC_V;
    #pragma unroll 4
    for (int i = threadIdx.x; i < VEC_V; i += THREADS) {
        float4 v = __ldg(&r[i]);
        unsigned m = __float_as_uint(v.x) | __float_as_uint(v.y) |
                     __float_as_uint(v.z) | __float_as_uint(v.w);
        if (m != 0u) {   // taken by exactly one thread in the whole block
            int off = __float_as_uint(v.x) ? 0 :
                      __float_as_uint(v.y) ? 1 :
                      __float_as_uint(v.z) ? 2 : 3;
            s_idx = i * 4 + off;
        }
    }
    __syncthreads();

    // ---- gather weight row -> out row (768 floats = 192 float4) ----
    const int idx = s_idx;
    const float4* wr = w   + (size_t)idx * VEC_E;
    float4*       o  = out + (size_t)row * VEC_E;
    for (int j = threadIdx.x; j < VEC_E; j += THREADS)
        o[j] = __ldg(&wr[j]);
}

extern "C" void kernel_launch(void* const* d_in, const int* in_sizes, int n_in,
                              void* d_out, int out_size)
{
    // metadata order: input (one-hot), weight. Defensive swap by size.
    const float4* oh = (const float4*)d_in[0];
    const float4* w  = (const float4*)d_in[1];
    if (n_in >= 2 && in_sizes[0] < in_sizes[1]) {  // weight (24.6M) < one-hot (32.8M)
        oh = (const float4*)d_in[1];
        w  = (const float4*)d_in[0];
    }
    onehot_embed_kernel<<<NROWS, THREADS>>>(oh, w, (float4*)d_out);
}

// round 4
// speedup vs baseline: 1.1693x; 1.1693x over previous
#include <cuda_runtime.h>
#include <cstdint>

// Problem: B=8, S=128, V=32000, E=768
// input:  one-hot [B,S,V] f32  (exactly one 1.0 per row, rest 0.0)
// weight: [V,E] f32
// out:    [B,S,E] f32 = weight[argmax(input[b,s,:]), :]
//
// Branch-free index recovery: idx = sum_i input[b,s,i] * i  (exact in fp32,
// since idx < 2^24 and the one-hot entries are exactly 0.0/1.0).

#define NROWS   1024          // B*S
#define VEC_V   8000          // V/4 float4 per row
#define VEC_E   192           // E/4 float4 per row
#define THREADS 256
#define NWARP   (THREADS/32)

__global__ __launch_bounds__(THREADS, 8)   // cap regs so 8 CTAs/SM -> single wave
void onehot_embed_kernel(const float4* __restrict__ oh,
                         const float4* __restrict__ w,
                         float4* __restrict__ out)
{
    __shared__ float s_part[NWARP];
    const int row = blockIdx.x;
    const int tid = threadIdx.x;
    const float4* __restrict__ r = oh + (size_t)row * VEC_V;

    // ---- branch-free scan: acc = sum(v[i] * global_index) ----
    float acc = 0.0f;
    int i = tid;
    #pragma unroll 1
    for (; i < VEC_V - 3 * THREADS; i += 4 * THREADS) {
        float4 v0 = __ldcs(&r[i]);
        float4 v1 = __ldcs(&r[i +     THREADS]);
        float4 v2 = __ldcs(&r[i + 2 * THREADS]);
        float4 v3 = __ldcs(&r[i + 3 * THREADS]);
        float b0 = (float)(4 * i);
        float b1 = (float)(4 * (i +     THREADS));
        float b2 = (float)(4 * (i + 2 * THREADS));
        float b3 = (float)(4 * (i + 3 * THREADS));
        acc += v0.x * b0 + v0.y * (b0 + 1.0f) + v0.z * (b0 + 2.0f) + v0.w * (b0 + 3.0f);
        acc += v1.x * b1 + v1.y * (b1 + 1.0f) + v1.z * (b1 + 2.0f) + v1.w * (b1 + 3.0f);
        acc += v2.x * b2 + v2.y * (b2 + 1.0f) + v2.z * (b2 + 2.0f) + v2.w * (b2 + 3.0f);
        acc += v3.x * b3 + v3.y * (b3 + 1.0f) + v3.z * (b3 + 2.0f) + v3.w * (b3 + 3.0f);
    }
    for (; i < VEC_V; i += THREADS) {
        float4 v = __ldcs(&r[i]);
        float b = (float)(4 * i);
        acc += v.x * b + v.y * (b + 1.0f) + v.z * (b + 2.0f) + v.w * (b + 3.0f);
    }

    // ---- reduce: warp shfl, then cross-warp via shared ----
    #pragma unroll
    for (int d = 16; d; d >>= 1)
        acc += __shfl_xor_sync(0xffffffffu, acc, d);
    if ((tid & 31) == 0) s_part[tid >> 5] = acc;
    __syncthreads();

    float total = 0.0f;
    #pragma unroll
    for (int wv = 0; wv < NWARP; wv++) total += s_part[wv];
    const int idx = (int)(total + 0.5f);

    // ---- gather weight row -> out row (768 floats = 192 float4) ----
    const float4* __restrict__ wr = w   + (size_t)idx * VEC_E;
    float4*       __restrict__ o  = out + (size_t)row * VEC_E;
    for (int j = tid; j < VEC_E; j += THREADS)
        o[j] = __ldg(&wr[j]);
}

extern "C" void kernel_launch(void* const* d_in, const int* in_sizes, int n_in,
                              void* d_out, int out_size)
{
    // metadata order: input (one-hot), weight. Defensive swap by size.
    const float4* oh = (const float4*)d_in[0];
    const float4* w  = (const float4*)d_in[1];
    if (n_in >= 2 && in_sizes[0] < in_sizes[1]) {  // weight (24.6M) < one-hot (32.8M)
        oh = (const float4*)d_in[1];
        w  = (const float4*)d_in[0];
    }
    onehot_embed_kernel<<<NROWS, THREADS>>>(oh, w, (float4*)d_out);
}

// round 6
// speedup vs baseline: 1.2666x; 1.0832x over previous
#include <cuda_runtime.h>
#include <cstdint>

// Problem: B=8, S=128, V=32000, E=768
// input:  one-hot [B,S,V] f32  (exactly one 1.0 per row, rest 0.0)
// weight: [V,E] f32
// out:    [B,S,E] f32 = weight[argnonzero(input[b,s,:]), :]
//
// Split each row into 4 quarter-segments (one CTA each, 4096 CTAs total) so
// HW CTA work-stealing (wave>=2) load-balances across SMs and the straggler
// tail shrinks to ~one quarter-scan. The segment containing the 1.0 detects
// it via a block-OR of raw bits, recovers the index from a branch-free
// iota dot product (exact in fp32 for idx < 2^24), and gathers the weight row.

#define NROWS   1024
#define VEC_V   8000          // float4 per row
#define SEGS    4
#define VEC_SEG 2000          // float4 per segment (32 KB)
#define VEC_E   192           // float4 per output row
#define THREADS 256
#define NWARP   (THREADS/32)

__global__ __launch_bounds__(THREADS, 8)
void onehot_embed_kernel(const float4* __restrict__ oh,
                         const float4* __restrict__ w,
                         float4* __restrict__ out)
{
    __shared__ float    s_acc[NWARP];
    __shared__ unsigned s_m[NWARP];

    const int unit = blockIdx.x;
    const int row  = unit >> 2;
    const int seg  = unit & 3;
    const int tid  = threadIdx.x;

    const float4* __restrict__ r = oh + (size_t)row * VEC_V + seg * VEC_SEG;
    const int gbase = seg * VEC_SEG;          // float4 index base within row

    float    acc = 0.0f;
    unsigned m   = 0u;

    // ---- batch 1: 4 unconditional loads (i = tid + {0,256,512,768}) ----
    {
        float4 v0 = __ldcs(&r[tid]);
        float4 v1 = __ldcs(&r[tid + 1 * THREADS]);
        float4 v2 = __ldcs(&r[tid + 2 * THREADS]);
        float4 v3 = __ldcs(&r[tid + 3 * THREADS]);
        float b0 = (float)(4 * (gbase + tid));
        float b1 = (float)(4 * (gbase + tid + 1 * THREADS));
        float b2 = (float)(4 * (gbase + tid + 2 * THREADS));
        float b3 = (float)(4 * (gbase + tid + 3 * THREADS));
        acc += v0.x * b0 + v0.y * (b0 + 1.0f) + v0.z * (b0 + 2.0f) + v0.w * (b0 + 3.0f);
        acc += v1.x * b1 + v1.y * (b1 + 1.0f) + v1.z * (b1 + 2.0f) + v1.w * (b1 + 3.0f);
        acc += v2.x * b2 + v2.y * (b2 + 1.0f) + v2.z * (b2 + 2.0f) + v2.w * (b2 + 3.0f);
        acc += v3.x * b3 + v3.y * (b3 + 1.0f) + v3.z * (b3 + 2.0f) + v3.w * (b3 + 3.0f);
        m |= __float_as_uint(v0.x) | __float_as_uint(v0.y) | __float_as_uint(v0.z) | __float_as_uint(v0.w);
        m |= __float_as_uint(v1.x) | __float_as_uint(v1.y) | __float_as_uint(v1.z) | __float_as_uint(v1.w);
        m |= __float_as_uint(v2.x) | __float_as_uint(v2.y) | __float_as_uint(v2.z) | __float_as_uint(v2.w);
        m |= __float_as_uint(v3.x) | __float_as_uint(v3.y) | __float_as_uint(v3.z) | __float_as_uint(v3.w);
    }
    // ---- batch 2: 3 unconditional + 1 predicated (2000 = 7*256 + 208) ----
    {
        float4 v0 = __ldcs(&r[tid + 4 * THREADS]);
        float4 v1 = __ldcs(&r[tid + 5 * THREADS]);
        float4 v2 = __ldcs(&r[tid + 6 * THREADS]);
        float4 v3 = make_float4(0.f, 0.f, 0.f, 0.f);
        const int i7 = tid + 7 * THREADS;
        if (i7 < VEC_SEG) v3 = __ldcs(&r[i7]);
        float b0 = (float)(4 * (gbase + tid + 4 * THREADS));
        float b1 = (float)(4 * (gbase + tid + 5 * THREADS));
        float b2 = (float)(4 * (gbase + tid + 6 * THREADS));
        float b3 = (float)(4 * (gbase + i7));
        acc += v0.x * b0 + v0.y * (b0 + 1.0f) + v0.z * (b0 + 2.0f) + v0.w * (b0 + 3.0f);
        acc += v1.x * b1 + v1.y * (b1 + 1.0f) + v1.z * (b1 + 2.0f) + v1.w * (b1 + 3.0f);
        acc += v2.x * b2 + v2.y * (b2 + 1.0f) + v2.z * (b2 + 2.0f) + v2.w * (b2 + 3.0f);
        acc += v3.x * b3 + v3.y * (b3 + 1.0f) + v3.z * (b3 + 2.0f) + v3.w * (b3 + 3.0f);
        m |= __float_as_uint(v0.x) | __float_as_uint(v0.y) | __float_as_uint(v0.z) | __float_as_uint(v0.w);
        m |= __float_as_uint(v1.x) | __float_as_uint(v1.y) | __float_as_uint(v1.z) | __float_as_uint(v1.w);
        m |= __float_as_uint(v2.x) | __float_as_uint(v2.y) | __float_as_uint(v2.z) | __float_as_uint(v2.w);
        m |= __float_as_uint(v3.x) | __float_as_uint(v3.y) | __float_as_uint(v3.z) | __float_as_uint(v3.w);
    }

    // ---- block reduce: float sum (index) + uint OR (found flag) ----
    #pragma unroll
    for (int d = 16; d; d >>= 1) {
        acc += __shfl_xor_sync(0xffffffffu, acc, d);
        m   |= __shfl_xor_sync(0xffffffffu, m, d);
    }
    if ((tid & 31) == 0) { s_acc[tid >> 5] = acc; s_m[tid >> 5] = m; }
    __syncthreads();

    float    total = 0.0f;
    unsigned found = 0u;
    #pragma unroll
    for (int wv = 0; wv < NWARP; wv++) { total += s_acc[wv]; found |= s_m[wv]; }

    // ---- the segment holding the 1.0 gathers the weight row ----
    if (found != 0u) {
        const int idx = (int)(total + 0.5f);
        const float4* __restrict__ wr = w   + (size_t)idx * VEC_E;
        float4*       __restrict__ o  = out + (size_t)row * VEC_E;
        if (tid < VEC_E)
            o[tid] = __ldg(&wr[tid]);
    }
}

extern "C" void kernel_launch(void* const* d_in, const int* in_sizes, int n_in,
                              void* d_out, int out_size)
{
    // metadata order: input (one-hot), weight. Defensive swap by size.
    const float4* oh = (const float4*)d_in[0];
    const float4* w  = (const float4*)d_in[1];
    if (n_in >= 2 && in_sizes[0] < in_sizes[1]) {  // weight (24.6M) < one-hot (32.8M)
        oh = (const float4*)d_in[1];
        w  = (const float4*)d_in[0];
    }
    onehot_embed_kernel<<<NROWS * SEGS, THREADS>>>(oh, w, (float4*)d_out);
}

// round 7
// speedup vs baseline: 1.2682x; 1.0013x over previous
#include <cuda_runtime.h>
#include <cstdint>

// Problem: B=8, S=128, V=32000, E=768
// input:  one-hot [B,S,V] f32  (exactly one 1.0 per row, rest 0.0)
// weight: [V,E] f32
// out:    [B,S,E] f32 = weight[argnonzero(input[b,s,:]), :]
//
// Each row is split into 8 segments (16 KB each, 8192 CTAs total): small CTA
// quanta let HW work-stealing pack the chip and shrink the drain tail. Each
// thread issues its ENTIRE load set (4x LDG.128) before consuming, maximizing
// front-batched MLP. The segment containing the 1.0 detects it via block-OR
// of raw bits, recovers the global index from an exact iota dot product
// (fp32-exact for idx < 2^24), and gathers the weight row itself.

#define NROWS   1024
#define VEC_V   8000          // float4 per row
#define SEGS    8
#define VEC_SEG 1000          // float4 per segment (16 KB)
#define VEC_E   192           // float4 per output row
#define THREADS 256
#define NWARP   (THREADS/32)

__global__ __launch_bounds__(THREADS, 8)
void onehot_embed_kernel(const float4* __restrict__ oh,
                         const float4* __restrict__ w,
                         float4* __restrict__ out)
{
    __shared__ float    s_acc[NWARP];
    __shared__ unsigned s_m[NWARP];

    const int unit = blockIdx.x;
    const int row  = unit >> 3;
    const int seg  = unit & 7;
    const int tid  = threadIdx.x;

    const float4* __restrict__ r = oh + (size_t)row * VEC_V + seg * VEC_SEG;
    const int gbase = seg * VEC_SEG;          // float4 index base within row

    // ---- single front-batched load set: 3 unconditional + 1 predicated ----
    // 1000 = 3*256 + 232
    const int i3 = tid + 3 * THREADS;
    float4 v0 = __ldcs(&r[tid]);
    float4 v1 = __ldcs(&r[tid + 1 * THREADS]);
    float4 v2 = __ldcs(&r[tid + 2 * THREADS]);
    float4 v3 = make_float4(0.f, 0.f, 0.f, 0.f);
    if (i3 < VEC_SEG) v3 = __ldcs(&r[i3]);

    // ---- consume: exact iota dot product + raw-bit OR ----
    float b0 = (float)(4 * (gbase + tid));
    float b1 = (float)(4 * (gbase + tid + 1 * THREADS));
    float b2 = (float)(4 * (gbase + tid + 2 * THREADS));
    float b3 = (float)(4 * (gbase + i3));

    float acc = 0.0f;
    acc += v0.x * b0 + v0.y * (b0 + 1.0f) + v0.z * (b0 + 2.0f) + v0.w * (b0 + 3.0f);
    acc += v1.x * b1 + v1.y * (b1 + 1.0f) + v1.z * (b1 + 2.0f) + v1.w * (b1 + 3.0f);
    acc += v2.x * b2 + v2.y * (b2 + 1.0f) + v2.z * (b2 + 2.0f) + v2.w * (b2 + 3.0f);
    acc += v3.x * b3 + v3.y * (b3 + 1.0f) + v3.z * (b3 + 2.0f) + v3.w * (b3 + 3.0f);

    unsigned m = 0u;
    m |= __float_as_uint(v0.x) | __float_as_uint(v0.y) | __float_as_uint(v0.z) | __float_as_uint(v0.w);
    m |= __float_as_uint(v1.x) | __float_as_uint(v1.y) | __float_as_uint(v1.z) | __float_as_uint(v1.w);
    m |= __float_as_uint(v2.x) | __float_as_uint(v2.y) | __float_as_uint(v2.z) | __float_as_uint(v2.w);
    m |= __float_as_uint(v3.x) | __float_as_uint(v3.y) | __float_as_uint(v3.z) | __float_as_uint(v3.w);

    // ---- block reduce: float sum (index) + uint OR (found flag) ----
    #pragma unroll
    for (int d = 16; d; d >>= 1) {
        acc += __shfl_xor_sync(0xffffffffu, acc, d);
        m   |= __shfl_xor_sync(0xffffffffu, m, d);
    }
    if ((tid & 31) == 0) { s_acc[tid >> 5] = acc; s_m[tid >> 5] = m; }
    __syncthreads();

    float    total = 0.0f;
    unsigned found = 0u;
    #pragma unroll
    for (int wv = 0; wv < NWARP; wv++) { total += s_acc[wv]; found |= s_m[wv]; }

    // ---- the segment holding the 1.0 gathers the weight row ----
    if (found != 0u) {
        const int idx = (int)(total + 0.5f);
        const float4* __restrict__ wr = w   + (size_t)idx * VEC_E;
        float4*       __restrict__ o  = out + (size_t)row * VEC_E;
        if (tid < VEC_E)
            o[tid] = __ldg(&wr[tid]);
    }
}

extern "C" void kernel_launch(void* const* d_in, const int* in_sizes, int n_in,
                              void* d_out, int out_size)
{
    // metadata order: input (one-hot), weight. Defensive swap by size.
    const float4* oh = (const float4*)d_in[0];
    const float4* w  = (const float4*)d_in[1];
    if (n_in >= 2 && in_sizes[0] < in_sizes[1]) {  // weight (24.6M) < one-hot (32.8M)
        oh = (const float4*)d_in[1];
        w  = (const float4*)d_in[0];
    }
    onehot_embed_kernel<<<NROWS * SEGS, THREADS>>>(oh, w, (float4*)d_out);
}